// round 16
// baseline (speedup 1.0000x reference)
#include <cuda_runtime.h>
#include <cuda_fp16.h>
#include <cstdint>

// GatedMemoryModule via mma.sync (HMMA) + ldmatrix, fp16 multi-pass split.
// out = g * softmax(x @ mem^T) @ mem + (1-g) * x,   g = sigmoid(x @ w + b)
// R14 (L1-byte cut):
//  - 32-row warp tiles: TN=256, 8 warps x 32 rows, 1 CTA/SM. Every GEMM B-fragment
//    ldmatrix now feeds 2 row-tiles -> B smem traffic per row halved.
//  - mem pre-converted to fp16 hi/lo ONCE per launch (setup kernel + __device__
//    scratch): main CTAs LDG ready fp16, no per-CTA mem conversion ALU.
//  - fp16 3-pass GEMM1 / 2-pass GEMM2 unchanged (rel_err ~1.3e-4).

#define TN       256
#define DDIM     128
#define MSLOT    64
#define NTHREADS 256

#define XSTR   272
#define MSTR   272
#define OFF_XH   0                      // 256*272 = 69632
#define OFF_XL   69632
#define OFF_MH   139264                 // 64*272 = 17408
#define OFF_ML   156672                 // -> 174080
#define OFF_GATE 174080                 // 256 f32
#define SMEM_BYTES 175104

// Pre-converted mem: 64*128 fp16 = 4096 u32 per tile.
__device__ uint32_t g_memh[4096];
__device__ uint32_t g_meml[4096];

__device__ __forceinline__ void mma16816(float* d, const uint32_t* a, const uint32_t* b) {
    asm volatile(
        "mma.sync.aligned.m16n8k16.row.col.f32.f16.f16.f32 "
        "{%0,%1,%2,%3}, {%4,%5,%6,%7}, {%8,%9}, {%0,%1,%2,%3};"
        : "+f"(d[0]), "+f"(d[1]), "+f"(d[2]), "+f"(d[3])
        : "r"(a[0]), "r"(a[1]), "r"(a[2]), "r"(a[3]), "r"(b[0]), "r"(b[1]));
}
__device__ __forceinline__ void ldsm4(uint32_t* r, uint32_t a) {
    asm volatile("ldmatrix.sync.aligned.m8n8.x4.shared.b16 {%0,%1,%2,%3}, [%4];"
                 : "=r"(r[0]), "=r"(r[1]), "=r"(r[2]), "=r"(r[3]) : "r"(a));
}
__device__ __forceinline__ void ldsm4t(uint32_t* r, uint32_t a) {
    asm volatile("ldmatrix.sync.aligned.m8n8.x4.trans.shared.b16 {%0,%1,%2,%3}, [%4];"
                 : "=r"(r[0]), "=r"(r[1]), "=r"(r[2]), "=r"(r[3]) : "r"(a));
}
__device__ __forceinline__ uint32_t smem_u32(const void* p) {
    uint32_t a;
    asm("{ .reg .u64 t; cvta.to.shared.u64 t, %1; cvt.u32.u64 %0, t; }" : "=r"(a) : "l"(p));
    return a;
}
__device__ __forceinline__ void split2h(float v, __half& h, __half& l) {
    h = __float2half_rn(v);
    l = __float2half_rn(v - __half2float(h));
}
__device__ __forceinline__ uint32_t packh(__half a, __half b) {
    __half2 p; p.x = a; p.y = b;
    return *(uint32_t*)&p;
}

// ---- setup: convert mem fp32 -> fp16 hi/lo in global (runs once per launch) ----
__global__ void convert_mem_kernel(const float* __restrict__ mem) {
    const int i = blockIdx.x * blockDim.x + threadIdx.x;   // 2048 float4
    if (i < MSLOT * DDIM / 4) {
        float4 v = ((const float4*)mem)[i];
        __half h0, l0, h1, l1, h2, l2, h3, l3;
        split2h(v.x, h0, l0); split2h(v.y, h1, l1);
        split2h(v.z, h2, l2); split2h(v.w, h3, l3);
        g_memh[2 * i]     = packh(h0, h1);
        g_memh[2 * i + 1] = packh(h2, h3);
        g_meml[2 * i]     = packh(l0, l1);
        g_meml[2 * i + 1] = packh(l2, l3);
    }
}

extern __shared__ char smc[];

__global__ void __launch_bounds__(NTHREADS, 1)
gated_memory_hmma(const float* __restrict__ x,
                  const float* __restrict__ gw, const float* __restrict__ gb,
                  float* __restrict__ out, int Ntot)
{
    const int tid = threadIdx.x;
    const int wid = tid >> 5;
    const int lane = tid & 31;
    const int qid = lane >> 2;
    const int qtr = lane & 3;
    const long long n0 = (long long)blockIdx.x * TN;
    const uint32_t sb = smem_u32(smc);
    const float gb0 = gb[0];

    // ===== Phase 0: stage X (convert) + pre-converted mem; gate dot folded in =====
    {
        const float4 wreg = ((const float4*)gw)[lane];
        const float4* x4 = (const float4*)x;
        #pragma unroll 4
        for (int i = tid; i < TN * DDIM / 4; i += NTHREADS) {
            int n = i >> 5, q = i & 31;          // warp covers one row; q == lane
            float4 v = make_float4(0.f, 0.f, 0.f, 0.f);
            if (n0 + n < (long long)Ntot) v = x4[(n0 + n) * (DDIM / 4) + q];
            __half h0, l0, h1, l1, h2, l2, h3, l3;
            split2h(v.x, h0, l0); split2h(v.y, h1, l1);
            split2h(v.z, h2, l2); split2h(v.w, h3, l3);
            char* ph = smc + OFF_XH + n * XSTR + q * 8;
            char* pl = smc + OFF_XL + n * XSTR + q * 8;
            ((uint32_t*)ph)[0] = packh(h0, h1); ((uint32_t*)ph)[1] = packh(h2, h3);
            ((uint32_t*)pl)[0] = packh(l0, l1); ((uint32_t*)pl)[1] = packh(l2, l3);
            float part = v.x * wreg.x + v.y * wreg.y + v.z * wreg.z + v.w * wreg.w;
            part += __shfl_xor_sync(0xffffffffu, part, 16);
            part += __shfl_xor_sync(0xffffffffu, part, 8);
            part += __shfl_xor_sync(0xffffffffu, part, 4);
            part += __shfl_xor_sync(0xffffffffu, part, 2);
            part += __shfl_xor_sync(0xffffffffu, part, 1);
            if (lane == 0) *(float*)(smc + OFF_GATE + 4 * n) = part;
        }
        // mem: 1024 uint4 per tile (16B = 8 fp16), 4 iters each
        const uint4* mh4 = (const uint4*)g_memh;
        const uint4* ml4 = (const uint4*)g_meml;
        #pragma unroll
        for (int jIt = tid; jIt < MSLOT * DDIM / 8; jIt += NTHREADS) {
            int row = jIt >> 4, c16 = jIt & 15;  // 16 uint4 per 128-fp16 row
            *(uint4*)(smc + OFF_MH + row * MSTR + c16 * 16) = mh4[jIt];
            *(uint4*)(smc + OFF_ML + row * MSTR + c16 * 16) = ml4[jIt];
        }
    }
    __syncthreads();

    const int r0 = wid * 32;

    // ldmatrix per-lane base addresses (lane -> matrix j = lane>>3, row = lane&7)
    const int Lm8 = lane & 7, j = lane >> 3;
    const uint32_t aBase0 = sb + OFF_XH + (uint32_t)((r0 + Lm8 + 8 * (j & 1)) * XSTR + (8 * (j >> 1)) * 2);
    const uint32_t aBase1 = aBase0 + 16 * XSTR;
    const uint32_t bBase  = sb + OFF_MH + (uint32_t)((Lm8 + 8 * (j >> 1)) * MSTR + (8 * (j & 1)) * 2);
    const uint32_t btBase = sb + OFF_MH + (uint32_t)((Lm8 + 8 * (j & 1)) * MSTR + (8 * (j >> 1)) * 2);

    // ===== GEMM1: S[32 x 64] = X @ Mem^T (fp16 3-pass); B shared by 2 row-tiles ====
    float acc1[2][8][4];
    #pragma unroll
    for (int rt = 0; rt < 2; rt++)
        #pragma unroll
        for (int nt = 0; nt < 8; nt++)
            #pragma unroll
            for (int jj = 0; jj < 4; jj++) acc1[rt][nt][jj] = 0.f;

    #pragma unroll
    for (int ks = 0; ks < 8; ks++) {
        uint32_t ah0[4], al0[4], ah1[4], al1[4];
        ldsm4(ah0, aBase0 + ks * 32);
        ldsm4(al0, aBase0 + ks * 32 + (OFF_XL - OFF_XH));
        ldsm4(ah1, aBase1 + ks * 32);
        ldsm4(al1, aBase1 + ks * 32 + (OFF_XL - OFF_XH));
        #pragma unroll
        for (int p = 0; p < 4; p++) {
            uint32_t bh[4], bl[4];
            uint32_t addr = bBase + (uint32_t)(p * 16 * MSTR) + ks * 32;
            ldsm4(bh, addr);
            ldsm4(bl, addr + (OFF_ML - OFF_MH));
            mma16816(acc1[0][2 * p],     ah0, bh);
            mma16816(acc1[0][2 * p],     ah0, bl + 0);
            mma16816(acc1[0][2 * p],     al0, bh);
            mma16816(acc1[0][2 * p + 1], ah0, bh + 2);
            mma16816(acc1[0][2 * p + 1], ah0, bl + 2);
            mma16816(acc1[0][2 * p + 1], al0, bh + 2);
            mma16816(acc1[1][2 * p],     ah1, bh);
            mma16816(acc1[1][2 * p],     ah1, bl + 0);
            mma16816(acc1[1][2 * p],     al1, bh);
            mma16816(acc1[1][2 * p + 1], ah1, bh + 2);
            mma16816(acc1[1][2 * p + 1], ah1, bl + 2);
            mma16816(acc1[1][2 * p + 1], al1, bh + 2);
        }
    }

    // ===== softmax + gate fold per row-tile (registers + quad shuffles) =====
    uint32_t a2h[2][4][4], a2l[2][4][4];
    float og[2][2];     // (1-g) for rows qid / qid+8 of each tile
    #pragma unroll
    for (int rt = 0; rt < 2; rt++) {
        float mxA = -1e30f, mxB = -1e30f;
        #pragma unroll
        for (int nt = 0; nt < 8; nt++) {
            mxA = fmaxf(mxA, fmaxf(acc1[rt][nt][0], acc1[rt][nt][1]));
            mxB = fmaxf(mxB, fmaxf(acc1[rt][nt][2], acc1[rt][nt][3]));
        }
        mxA = fmaxf(mxA, __shfl_xor_sync(0xffffffffu, mxA, 1));
        mxA = fmaxf(mxA, __shfl_xor_sync(0xffffffffu, mxA, 2));
        mxB = fmaxf(mxB, __shfl_xor_sync(0xffffffffu, mxB, 1));
        mxB = fmaxf(mxB, __shfl_xor_sync(0xffffffffu, mxB, 2));
        float smA = 0.f, smB = 0.f;
        #pragma unroll
        for (int nt = 0; nt < 8; nt++) {
            acc1[rt][nt][0] = __expf(acc1[rt][nt][0] - mxA);
            acc1[rt][nt][1] = __expf(acc1[rt][nt][1] - mxA);
            acc1[rt][nt][2] = __expf(acc1[rt][nt][2] - mxB);
            acc1[rt][nt][3] = __expf(acc1[rt][nt][3] - mxB);
            smA += acc1[rt][nt][0] + acc1[rt][nt][1];
            smB += acc1[rt][nt][2] + acc1[rt][nt][3];
        }
        smA += __shfl_xor_sync(0xffffffffu, smA, 1);
        smA += __shfl_xor_sync(0xffffffffu, smA, 2);
        smB += __shfl_xor_sync(0xffffffffu, smB, 1);
        smB += __shfl_xor_sync(0xffffffffu, smB, 2);
        const float gdA = *(float*)(smc + OFF_GATE + 4 * (r0 + 16 * rt + qid));
        const float gdB = *(float*)(smc + OFF_GATE + 4 * (r0 + 16 * rt + qid + 8));
        const float gA = 1.f / (1.f + __expf(-(gdA + gb0)));
        const float gB = 1.f / (1.f + __expf(-(gdB + gb0)));
        const float scA = gA / smA, scB = gB / smB;
        og[rt][0] = 1.f - gA;
        og[rt][1] = 1.f - gB;
        #pragma unroll
        for (int ks = 0; ks < 4; ks++) {
            #pragma unroll
            for (int half = 0; half < 2; half++) {
                const int nt = 2 * ks + half;
                __half h0, l0, h1, l1, h2, l2, h3, l3;
                split2h(acc1[rt][nt][0] * scA, h0, l0);
                split2h(acc1[rt][nt][1] * scA, h1, l1);
                split2h(acc1[rt][nt][2] * scB, h2, l2);
                split2h(acc1[rt][nt][3] * scB, h3, l3);
                a2h[rt][ks][2 * half]     = packh(h0, h1);
                a2h[rt][ks][2 * half + 1] = packh(h2, h3);
                a2l[rt][ks][2 * half]     = packh(l0, l1);
                a2l[rt][ks][2 * half + 1] = packh(l2, l3);
            }
        }
    }

    // ===== GEMM2 (fp16 2-pass, hi mem only; B shared by 2 row-tiles) + epilogue ====
    #pragma unroll
    for (int h = 0; h < 2; h++) {
        float acc2[2][8][4];
        #pragma unroll
        for (int rt = 0; rt < 2; rt++)
            #pragma unroll
            for (int nt = 0; nt < 8; nt++)
                #pragma unroll
                for (int jj = 0; jj < 4; jj++) acc2[rt][nt][jj] = 0.f;

        #pragma unroll
        for (int ks = 0; ks < 4; ks++) {
            const uint32_t rowAddr = btBase + (uint32_t)(ks * 16 * MSTR);
            #pragma unroll
            for (int p = 0; p < 4; p++) {
                uint32_t bh[4];
                ldsm4t(bh, rowAddr + (uint32_t)((4 * h + p) * 32));
                mma16816(acc2[0][2 * p],     a2h[0][ks], bh);
                mma16816(acc2[0][2 * p],     a2l[0][ks], bh);
                mma16816(acc2[0][2 * p + 1], a2h[0][ks], bh + 2);
                mma16816(acc2[0][2 * p + 1], a2l[0][ks], bh + 2);
                mma16816(acc2[1][2 * p],     a2h[1][ks], bh);
                mma16816(acc2[1][2 * p],     a2l[1][ks], bh);
                mma16816(acc2[1][2 * p + 1], a2h[1][ks], bh + 2);
                mma16816(acc2[1][2 * p + 1], a2l[1][ks], bh + 2);
            }
        }

        #pragma unroll
        for (int rt = 0; rt < 2; rt++) {
            const int rA = r0 + 16 * rt + qid, rB = rA + 8;
            const bool okA = (n0 + rA < (long long)Ntot), okB = (n0 + rB < (long long)Ntot);
            float* outA = out + (n0 + rA) * DDIM;
            float* outB = out + (n0 + rB) * DDIM;
            const float ogA = og[rt][0], ogB = og[rt][1];
            #pragma unroll
            for (int nt = 0; nt < 8; nt++) {
                const int c = (8 * h + nt) * 8 + qtr * 2;
                uint32_t xhA = *(uint32_t*)(smc + OFF_XH + rA * XSTR + c * 2);
                uint32_t xlA = *(uint32_t*)(smc + OFF_XL + rA * XSTR + c * 2);
                uint32_t xhB = *(uint32_t*)(smc + OFF_XH + rB * XSTR + c * 2);
                uint32_t xlB = *(uint32_t*)(smc + OFF_XL + rB * XSTR + c * 2);
                float2 hA = __half22float2(*(__half2*)&xhA), lA = __half22float2(*(__half2*)&xlA);
                float2 hB = __half22float2(*(__half2*)&xhB), lB = __half22float2(*(__half2*)&xlB);
                float2 oA, oB;
                oA.x = ogA * (hA.x + lA.x) + acc2[rt][nt][0];
                oA.y = ogA * (hA.y + lA.y) + acc2[rt][nt][1];
                oB.x = ogB * (hB.x + lB.x) + acc2[rt][nt][2];
                oB.y = ogB * (hB.y + lB.y) + acc2[rt][nt][3];
                if (okA) *(float2*)(outA + c) = oA;
                if (okB) *(float2*)(outB + c) = oB;
            }
        }
    }
}

extern "C" void kernel_launch(void* const* d_in, const int* in_sizes, int n_in,
                              void* d_out, int out_size)
{
    const float* x   = (const float*)d_in[0];
    const float* mem = (const float*)d_in[1];
    const float* gw  = (const float*)d_in[2];
    const float* gb  = (const float*)d_in[3];
    float* out = (float*)d_out;

    const int Ntot = in_sizes[0] / DDIM;
    const int grid = (Ntot + TN - 1) / TN;

    convert_mem_kernel<<<(MSLOT * DDIM / 4 + 255) / 256, 256>>>(mem);
    cudaFuncSetAttribute(gated_memory_hmma,
                         cudaFuncAttributeMaxDynamicSharedMemorySize, SMEM_BYTES);
    gated_memory_hmma<<<grid, NTHREADS, SMEM_BYTES>>>(x, gw, gb, out, Ntot);
}

// round 17
// speedup vs baseline: 1.6543x; 1.6543x over previous
#include <cuda_runtime.h>
#include <cuda_fp16.h>
#include <cstdint>

// GatedMemoryModule via mma.sync (HMMA) + ldmatrix, fp16 multi-pass split.
// out = g * softmax(x @ mem^T) @ mem + (1-g) * x,   g = sigmoid(x @ w + b)
// R16 = R13 shape (TN=128, 16-row warp tiles, 2 CTAs/SM, 128 regs) +
//  - mem pre-converted to fp16 hi/lo once per launch (setup kernel + __device__
//    scratch): main CTAs do pure uint4 copies, no per-CTA conversion ALU
//  - epilogue x re-load via ldmatrix.x4 (A-fragment positions == epilogue
//    positions): 64 scalar LDS.32 -> 16 ldsm issues per thread
// R14's 32-row tiles reverted: they spilled (255 regs) and halved occupancy.

#define TN       128
#define DDIM     128
#define MSLOT    64
#define NTHREADS 256

// fp16 row strides padded: stride % 128 == 16 bytes -> conflict-free ldmatrix rows.
#define XSTR   272
#define MSTR   272
#define OFF_XH   0                      // 128*272 = 34816
#define OFF_XL   34816
#define OFF_MH   69632                  // 64*272 = 17408
#define OFF_ML   87040                  // -> 104448
#define OFF_GATE 104448                 // 128 f32 (raw gate dot)
#define SMEM_BYTES 104960

// Pre-converted mem: 64*128 fp16 = 4096 u32 per tile.
__device__ uint32_t g_memh[4096];
__device__ uint32_t g_meml[4096];

__device__ __forceinline__ void mma16816(float* d, const uint32_t* a, const uint32_t* b) {
    asm volatile(
        "mma.sync.aligned.m16n8k16.row.col.f32.f16.f16.f32 "
        "{%0,%1,%2,%3}, {%4,%5,%6,%7}, {%8,%9}, {%0,%1,%2,%3};"
        : "+f"(d[0]), "+f"(d[1]), "+f"(d[2]), "+f"(d[3])
        : "r"(a[0]), "r"(a[1]), "r"(a[2]), "r"(a[3]), "r"(b[0]), "r"(b[1]));
}
__device__ __forceinline__ void ldsm4(uint32_t* r, uint32_t a) {
    asm volatile("ldmatrix.sync.aligned.m8n8.x4.shared.b16 {%0,%1,%2,%3}, [%4];"
                 : "=r"(r[0]), "=r"(r[1]), "=r"(r[2]), "=r"(r[3]) : "r"(a));
}
__device__ __forceinline__ void ldsm4t(uint32_t* r, uint32_t a) {
    asm volatile("ldmatrix.sync.aligned.m8n8.x4.trans.shared.b16 {%0,%1,%2,%3}, [%4];"
                 : "=r"(r[0]), "=r"(r[1]), "=r"(r[2]), "=r"(r[3]) : "r"(a));
}
__device__ __forceinline__ uint32_t smem_u32(const void* p) {
    uint32_t a;
    asm("{ .reg .u64 t; cvta.to.shared.u64 t, %1; cvt.u32.u64 %0, t; }" : "=r"(a) : "l"(p));
    return a;
}
__device__ __forceinline__ void split2h(float v, __half& h, __half& l) {
    h = __float2half_rn(v);
    l = __float2half_rn(v - __half2float(h));
}
__device__ __forceinline__ uint32_t packh(__half a, __half b) {
    __half2 p; p.x = a; p.y = b;
    return *(uint32_t*)&p;
}

// ---- setup: convert mem fp32 -> fp16 hi/lo in global (runs once per launch) ----
__global__ void convert_mem_kernel(const float* __restrict__ mem) {
    const int i = blockIdx.x * blockDim.x + threadIdx.x;   // 2048 float4
    if (i < MSLOT * DDIM / 4) {
        float4 v = ((const float4*)mem)[i];
        __half h0, l0, h1, l1, h2, l2, h3, l3;
        split2h(v.x, h0, l0); split2h(v.y, h1, l1);
        split2h(v.z, h2, l2); split2h(v.w, h3, l3);
        g_memh[2 * i]     = packh(h0, h1);
        g_memh[2 * i + 1] = packh(h2, h3);
        g_meml[2 * i]     = packh(l0, l1);
        g_meml[2 * i + 1] = packh(l2, l3);
    }
}

extern __shared__ char smc[];

__global__ void __launch_bounds__(NTHREADS, 2)
gated_memory_hmma(const float* __restrict__ x,
                  const float* __restrict__ gw, const float* __restrict__ gb,
                  float* __restrict__ out, int Ntot)
{
    const int tid = threadIdx.x;
    const int wid = tid >> 5;
    const int lane = tid & 31;
    const int qid = lane >> 2;
    const int qtr = lane & 3;
    const long long n0 = (long long)blockIdx.x * TN;
    const uint32_t sb = smem_u32(smc);
    const float gb0 = gb[0];

    // ===== Phase 0: stage X (convert) + pre-converted mem; gate dot folded in =====
    {
        const float4 wreg = ((const float4*)gw)[lane];
        const float4* x4 = (const float4*)x;
        #pragma unroll
        for (int i = tid; i < TN * DDIM / 4; i += NTHREADS) {
            int n = i >> 5, q = i & 31;          // warp covers one row; q == lane
            float4 v = make_float4(0.f, 0.f, 0.f, 0.f);
            if (n0 + n < (long long)Ntot) v = x4[(n0 + n) * (DDIM / 4) + q];
            __half h0, l0, h1, l1, h2, l2, h3, l3;
            split2h(v.x, h0, l0); split2h(v.y, h1, l1);
            split2h(v.z, h2, l2); split2h(v.w, h3, l3);
            char* ph = smc + OFF_XH + n * XSTR + q * 8;
            char* pl = smc + OFF_XL + n * XSTR + q * 8;
            ((uint32_t*)ph)[0] = packh(h0, h1); ((uint32_t*)ph)[1] = packh(h2, h3);
            ((uint32_t*)pl)[0] = packh(l0, l1); ((uint32_t*)pl)[1] = packh(l2, l3);
            float part = v.x * wreg.x + v.y * wreg.y + v.z * wreg.z + v.w * wreg.w;
            part += __shfl_xor_sync(0xffffffffu, part, 16);
            part += __shfl_xor_sync(0xffffffffu, part, 8);
            part += __shfl_xor_sync(0xffffffffu, part, 4);
            part += __shfl_xor_sync(0xffffffffu, part, 2);
            part += __shfl_xor_sync(0xffffffffu, part, 1);
            if (lane == 0) *(float*)(smc + OFF_GATE + 4 * n) = part;
        }
        // mem: pure copies of pre-converted fp16 (1024 uint4 per tile)
        const uint4* mh4 = (const uint4*)g_memh;
        const uint4* ml4 = (const uint4*)g_meml;
        #pragma unroll
        for (int i = tid; i < MSLOT * DDIM / 8; i += NTHREADS) {
            int row = i >> 4, c16 = i & 15;      // 16 uint4 per 128-fp16 row
            *(uint4*)(smc + OFF_MH + row * MSTR + c16 * 16) = mh4[i];
            *(uint4*)(smc + OFF_ML + row * MSTR + c16 * 16) = ml4[i];
        }
    }
    __syncthreads();

    const int r0 = wid * 16;

    // ldmatrix per-lane base addresses (lane -> matrix j = lane>>3, row = lane&7)
    const int Lm8 = lane & 7, j = lane >> 3;
    const uint32_t aBase  = sb + OFF_XH + (uint32_t)((r0 + Lm8 + 8 * (j & 1)) * XSTR + (8 * (j >> 1)) * 2);
    const uint32_t bBase  = sb + OFF_MH + (uint32_t)((Lm8 + 8 * (j >> 1)) * MSTR + (8 * (j & 1)) * 2);
    const uint32_t btBase = sb + OFF_MH + (uint32_t)((Lm8 + 8 * (j & 1)) * MSTR + (8 * (j >> 1)) * 2);

    // ===== GEMM1: S[16 x 64] = X @ Mem^T (fp16 3-pass) =====
    float acc1[8][4];
    #pragma unroll
    for (int nt = 0; nt < 8; nt++)
        #pragma unroll
        for (int jj = 0; jj < 4; jj++) acc1[nt][jj] = 0.f;

    #pragma unroll
    for (int ks = 0; ks < 8; ks++) {
        uint32_t ah[4], al[4];
        ldsm4(ah, aBase + ks * 32);
        ldsm4(al, aBase + ks * 32 + (OFF_XL - OFF_XH));
        #pragma unroll
        for (int p = 0; p < 4; p++) {
            uint32_t bh[4], bl[4];
            uint32_t addr = bBase + (uint32_t)(p * 16 * MSTR) + ks * 32;
            ldsm4(bh, addr);
            ldsm4(bl, addr + (OFF_ML - OFF_MH));
            mma16816(acc1[2 * p],     ah, bh);
            mma16816(acc1[2 * p],     ah, bl + 0);
            mma16816(acc1[2 * p],     al, bh);
            mma16816(acc1[2 * p + 1], ah, bh + 2);
            mma16816(acc1[2 * p + 1], ah, bl + 2);
            mma16816(acc1[2 * p + 1], al, bh + 2);
        }
    }

    // ===== softmax + gate fold (registers + quad shuffles) =====
    float mxA = -1e30f, mxB = -1e30f;
    #pragma unroll
    for (int nt = 0; nt < 8; nt++) {
        mxA = fmaxf(mxA, fmaxf(acc1[nt][0], acc1[nt][1]));
        mxB = fmaxf(mxB, fmaxf(acc1[nt][2], acc1[nt][3]));
    }
    mxA = fmaxf(mxA, __shfl_xor_sync(0xffffffffu, mxA, 1));
    mxA = fmaxf(mxA, __shfl_xor_sync(0xffffffffu, mxA, 2));
    mxB = fmaxf(mxB, __shfl_xor_sync(0xffffffffu, mxB, 1));
    mxB = fmaxf(mxB, __shfl_xor_sync(0xffffffffu, mxB, 2));
    float smA = 0.f, smB = 0.f;
    #pragma unroll
    for (int nt = 0; nt < 8; nt++) {
        acc1[nt][0] = __expf(acc1[nt][0] - mxA);
        acc1[nt][1] = __expf(acc1[nt][1] - mxA);
        acc1[nt][2] = __expf(acc1[nt][2] - mxB);
        acc1[nt][3] = __expf(acc1[nt][3] - mxB);
        smA += acc1[nt][0] + acc1[nt][1];
        smB += acc1[nt][2] + acc1[nt][3];
    }
    smA += __shfl_xor_sync(0xffffffffu, smA, 1);
    smA += __shfl_xor_sync(0xffffffffu, smA, 2);
    smB += __shfl_xor_sync(0xffffffffu, smB, 1);
    smB += __shfl_xor_sync(0xffffffffu, smB, 2);
    const float gdA = *(float*)(smc + OFF_GATE + 4 * (r0 + qid));
    const float gdB = *(float*)(smc + OFF_GATE + 4 * (r0 + qid + 8));
    const float gA = 1.f / (1.f + __expf(-(gdA + gb0)));
    const float gB = 1.f / (1.f + __expf(-(gdB + gb0)));
    const float scA = gA / smA;     // fold g into attn -> GEMM2 yields g*read
    const float scB = gB / smB;
    const float ogA = 1.f - gA, ogB = 1.f - gB;

    // C-frag layout == A-frag layout: convert in registers (fp16 hi/lo).
    uint32_t a2h[4][4], a2l[4][4];
    #pragma unroll
    for (int ks = 0; ks < 4; ks++) {
        #pragma unroll
        for (int half = 0; half < 2; half++) {
            const int nt = 2 * ks + half;
            __half h0, l0, h1, l1, h2, l2, h3, l3;
            split2h(acc1[nt][0] * scA, h0, l0);
            split2h(acc1[nt][1] * scA, h1, l1);
            split2h(acc1[nt][2] * scB, h2, l2);
            split2h(acc1[nt][3] * scB, h3, l3);
            a2h[ks][2 * half]     = packh(h0, h1);
            a2h[ks][2 * half + 1] = packh(h2, h3);
            a2l[ks][2 * half]     = packh(l0, l1);
            a2l[ks][2 * half + 1] = packh(l2, l3);
        }
    }

    // ===== GEMM2 (fp16 2-pass, hi mem tile only) + fused fragment epilogue =====
    const int rA = r0 + qid, rB = rA + 8;
    const bool okA = (n0 + rA < (long long)Ntot), okB = (n0 + rB < (long long)Ntot);
    float* outA = out + (n0 + rA) * DDIM;
    float* outB = out + (n0 + rB) * DDIM;

    #pragma unroll
    for (int h = 0; h < 2; h++) {
        float acc2[8][4];
        #pragma unroll
        for (int nt = 0; nt < 8; nt++)
            #pragma unroll
            for (int jj = 0; jj < 4; jj++) acc2[nt][jj] = 0.f;

        #pragma unroll
        for (int ks = 0; ks < 4; ks++) {
            const uint32_t rowAddr = btBase + (uint32_t)(ks * 16 * MSTR);
            #pragma unroll
            for (int p = 0; p < 4; p++) {
                uint32_t bh[4];
                ldsm4t(bh, rowAddr + (uint32_t)((4 * h + p) * 32));
                mma16816(acc2[2 * p],     a2h[ks], bh);
                mma16816(acc2[2 * p],     a2l[ks], bh);
                mma16816(acc2[2 * p + 1], a2h[ks], bh + 2);
                mma16816(acc2[2 * p + 1], a2l[ks], bh + 2);
            }
        }

        // epilogue for this half: out = (1-g)*x + g*read.
        // x re-loaded via ldmatrix: A-frag k-tile (4h+ks) regs {0,1,2,3} sit exactly
        // at (rA,c),(rB,c),(rA,c+8),(rB,c+8) for c = 64h+16ks+2qtr.
        #pragma unroll
        for (int ks = 0; ks < 4; ks++) {
            uint32_t xh[4], xl[4];
            ldsm4(xh, aBase + (uint32_t)((4 * h + ks) * 32));
            ldsm4(xl, aBase + (uint32_t)((4 * h + ks) * 32) + (OFF_XL - OFF_XH));
            #pragma unroll
            for (int half = 0; half < 2; half++) {       // half 0: regs 0,1 ; 1: regs 2,3
                const int nt = 2 * ks + half;
                const int c = 64 * h + 16 * ks + 8 * half + qtr * 2;
                float2 hA = __half22float2(*(__half2*)&xh[2 * half]);
                float2 lA = __half22float2(*(__half2*)&xl[2 * half]);
                float2 hB = __half22float2(*(__half2*)&xh[2 * half + 1]);
                float2 lB = __half22float2(*(__half2*)&xl[2 * half + 1]);
                float2 oA, oB;
                oA.x = ogA * (hA.x + lA.x) + acc2[nt][0];
                oA.y = ogA * (hA.y + lA.y) + acc2[nt][1];
                oB.x = ogB * (hB.x + lB.x) + acc2[nt][2];
                oB.y = ogB * (hB.y + lB.y) + acc2[nt][3];
                if (okA) *(float2*)(outA + c) = oA;
                if (okB) *(float2*)(outB + c) = oB;
            }
        }
    }
}

extern "C" void kernel_launch(void* const* d_in, const int* in_sizes, int n_in,
                              void* d_out, int out_size)
{
    const float* x   = (const float*)d_in[0];
    const float* mem = (const float*)d_in[1];
    const float* gw  = (const float*)d_in[2];
    const float* gb  = (const float*)d_in[3];
    float* out = (float*)d_out;

    const int Ntot = in_sizes[0] / DDIM;
    const int grid = (Ntot + TN - 1) / TN;

    convert_mem_kernel<<<(MSLOT * DDIM / 4 + 255) / 256, 256>>>(mem);
    cudaFuncSetAttribute(gated_memory_hmma,
                         cudaFuncAttributeMaxDynamicSharedMemorySize, SMEM_BYTES);
    gated_memory_hmma<<<grid, NTHREADS, SMEM_BYTES>>>(x, gw, gb, out, Ntot);
}